// round 9
// baseline (speedup 1.0000x reference)
#include <cuda_runtime.h>
#include <cstdint>

#define N_NODES 50000
#define N_EDGES 800000
#define IN_F 256
#define HID 128
#define OUT_F 64

#define SCAN_B 512
#define SCAN_NBLK ((N_NODES + SCAN_B - 1) / SCAN_B)   // 98

// ---------------- scratch (device globals; no allocs allowed) ----------------
__device__ __align__(16) float g_m1[(size_t)N_NODES * HID];    // (x*ns) @ W1
__device__ __align__(16) float g_agg1[(size_t)N_NODES * HID];  // gather accum, layer 1
__device__ __align__(16) float g_m2[(size_t)N_NODES * OUT_F];  // (h*ns) @ W2
__device__ float g_ns[N_NODES];                  // deg_out^-1/2 (clamped)
__device__ float g_nd[N_NODES];                  // deg_in^-1/2 (clamped)
__device__ int   g_degs[N_NODES];                // out-degree (src)
__device__ int   g_degd[N_NODES];                // in-degree (dst)
__device__ int   g_rowptr[N_NODES + 1];          // CSR by dst
__device__ int   g_cur[N_NODES];                 // fill cursors
__device__ int   g_esrc[N_EDGES];                // src id per bucketed edge
__device__ int   g_src[N_EDGES];                 // normalized (int, clamped) src
__device__ int   g_dst[N_EDGES];                 // normalized (int, clamped) dst
__device__ int   g_bsum[SCAN_NBLK];
__device__ int   g_boff[SCAN_NBLK];
__device__ int   g_is32;                         // 1 if index arrays are int32

// ---------------- init ------------------------------------------------------
__global__ void k_init() {
    int i = blockIdx.x * blockDim.x + threadIdx.x;
    if (i < N_NODES) { g_degs[i] = 0; g_degd[i] = 0; g_cur[i] = 0; }
    if (i == 0) g_is32 = 0;
}

// ---------------- dtype detect: int32 vs int64 indices -----------------------
// Reading the first N_EDGES int32 words is safe for BOTH dtypes. If the data
// is little-endian int64 with values < 2^31, every odd word is 0.
__global__ void k_detect(const int* __restrict__ sw, const int* __restrict__ dw) {
    int t = blockIdx.x * 256 + threadIdx.x;
    int v = 0;
    if (t < N_EDGES / 2) v = sw[2 * t + 1] | dw[2 * t + 1];
    unsigned any = __ballot_sync(0xffffffffu, v != 0);
    if ((threadIdx.x & 31) == 0 && any) atomicOr(&g_is32, 1);
}

// ---------------- normalize indices to clamped int ---------------------------
__global__ void k_cvt(const void* __restrict__ srcp, const void* __restrict__ dstp) {
    int e = blockIdx.x * 256 + threadIdx.x;
    if (e >= N_EDGES) return;
    int s, d;
    if (g_is32) {
        s = ((const int*)srcp)[e];
        d = ((const int*)dstp)[e];
    } else {
        s = (int)((const long long*)srcp)[e];
        d = (int)((const long long*)dstp)[e];
    }
    s = min(max(s, 0), N_NODES - 1);
    d = min(max(d, 0), N_NODES - 1);
    g_src[e] = s;
    g_dst[e] = d;
}

// ---------------- degrees ----------------------------------------------------
__global__ void k_deg() {
    int e = blockIdx.x * blockDim.x + threadIdx.x;
    if (e >= N_EDGES) return;
    atomicAdd(&g_degs[g_src[e]], 1);
    atomicAdd(&g_degd[g_dst[e]], 1);
}

__global__ void k_norms() {
    int i = blockIdx.x * blockDim.x + threadIdx.x;
    if (i >= N_NODES) return;
    int ds = g_degs[i]; if (ds < 1) ds = 1;
    int dd = g_degd[i]; if (dd < 1) dd = 1;
    g_ns[i] = rsqrtf((float)ds);
    g_nd[i] = rsqrtf((float)dd);
}

// ---------------- prefix scan of in-degrees -> rowptr ------------------------
__global__ void k_scan1() {
    __shared__ int sh[SCAN_B];
    int i = blockIdx.x * SCAN_B + threadIdx.x;
    int v = (i < N_NODES) ? g_degd[i] : 0;
    sh[threadIdx.x] = v;
    __syncthreads();
    #pragma unroll
    for (int off = 1; off < SCAN_B; off <<= 1) {
        int t = (threadIdx.x >= off) ? sh[threadIdx.x - off] : 0;
        __syncthreads();
        sh[threadIdx.x] += t;
        __syncthreads();
    }
    if (i < N_NODES) g_rowptr[i] = sh[threadIdx.x] - v;   // exclusive
    if (threadIdx.x == SCAN_B - 1) g_bsum[blockIdx.x] = sh[threadIdx.x];
}

__global__ void k_scan2() {
    if (threadIdx.x == 0) {
        int acc = 0;
        for (int b = 0; b < SCAN_NBLK; b++) { int t = g_bsum[b]; g_boff[b] = acc; acc += t; }
    }
}

__global__ void k_scan3() {
    int i = blockIdx.x * SCAN_B + threadIdx.x;
    if (i < N_NODES) g_rowptr[i] += g_boff[blockIdx.x];
    if (i == 0) g_rowptr[N_NODES] = N_EDGES;
}

// ---------------- bucket fill: edges grouped by dst --------------------------
__global__ void k_fill() {
    int e = blockIdx.x * blockDim.x + threadIdx.x;
    if (e >= N_EDGES) return;
    int d = g_dst[e];
    int pos = g_rowptr[d] + atomicAdd(&g_cur[d], 1);
    if (pos >= 0 && pos < N_EDGES) g_esrc[pos] = g_src[e];
}

// ---------------- GEMM1: m1 = (x .* ns) @ W1  (50000x256 @ 256x128) ----------
// Classic tiled SGEMM: 128x128 tile, 256 threads, 8x8 microtile, KC=16.
// Static smem only (16.5 KB) — no cudaFuncSetAttribute needed.
#define KC 16
__global__ void __launch_bounds__(256)
k_gemm1(const float* __restrict__ x, const float* __restrict__ W1) {
    __shared__ float xs[KC][132];   // [k][m], padded to dodge STS conflicts
    __shared__ float ws[KC][128];   // [k][n]
    int t = threadIdx.x;
    int base = blockIdx.x * 128;
    int m0 = (t >> 4) * 8;
    int n0 = (t & 15) * 8;
    float acc[8][8] = {};

    for (int k0 = 0; k0 < IN_F; k0 += KC) {
        __syncthreads();
        // ws: W1 rows k0..k0+15, all 128 cols (already [k][n] contiguous)
        #pragma unroll
        for (int f = t; f < 512; f += 256) {
            int kk = f >> 5;
            int nn = (f & 31) * 4;
            *(float4*)(&ws[kk][nn]) = *(const float4*)(W1 + (k0 + kk) * HID + nn);
        }
        // xs: x rows (scaled by ns), transposed into [k][m]
        #pragma unroll
        for (int f = t; f < 512; f += 256) {
            int mm = f >> 2;
            int k4 = (f & 3) * 4;
            int node = base + mm; if (node >= N_NODES) node = N_NODES - 1;
            float ns = g_ns[node];
            float4 v = *(const float4*)(x + (size_t)node * IN_F + k0 + k4);
            xs[k4 + 0][mm] = v.x * ns;
            xs[k4 + 1][mm] = v.y * ns;
            xs[k4 + 2][mm] = v.z * ns;
            xs[k4 + 3][mm] = v.w * ns;
        }
        __syncthreads();
        #pragma unroll
        for (int k = 0; k < KC; k++) {
            float a[8], b[8];
            *(float4*)(a)     = *(float4*)(&xs[k][m0]);
            *(float4*)(a + 4) = *(float4*)(&xs[k][m0 + 4]);
            *(float4*)(b)     = *(float4*)(&ws[k][n0]);
            *(float4*)(b + 4) = *(float4*)(&ws[k][n0 + 4]);
            #pragma unroll
            for (int i = 0; i < 8; i++)
                #pragma unroll
                for (int j = 0; j < 8; j++)
                    acc[i][j] += a[i] * b[j];
        }
    }
    #pragma unroll
    for (int i = 0; i < 8; i++) {
        int node = base + m0 + i;
        if (node < N_NODES) {
            *(float4*)(g_m1 + (size_t)node * HID + n0)     = *(float4*)(&acc[i][0]);
            *(float4*)(g_m1 + (size_t)node * HID + n0 + 4) = *(float4*)(&acc[i][4]);
        }
    }
}

// ---------------- agg1: gather-sum m1 rows per dst (CSR) ---------------------
// one warp per node; lane l owns float4 l of the 128-float row
__global__ void __launch_bounds__(256)
k_agg1() {
    int n = (blockIdx.x * 256 + threadIdx.x) >> 5;
    if (n >= N_NODES) return;
    int l = threadIdx.x & 31;
    int s0 = g_rowptr[n];
    int e1 = g_rowptr[n + 1];
    float4 acc = make_float4(0.f, 0.f, 0.f, 0.f);
    int e = s0;
    for (; e + 1 < e1; e += 2) {
        int sa = g_esrc[e];
        int sb = g_esrc[e + 1];
        float4 va = ((const float4*)(g_m1 + (size_t)sa * HID))[l];
        float4 vb = ((const float4*)(g_m1 + (size_t)sb * HID))[l];
        acc.x += va.x + vb.x;
        acc.y += va.y + vb.y;
        acc.z += va.z + vb.z;
        acc.w += va.w + vb.w;
    }
    if (e < e1) {
        int sa = g_esrc[e];
        float4 va = ((const float4*)(g_m1 + (size_t)sa * HID))[l];
        acc.x += va.x; acc.y += va.y; acc.z += va.z; acc.w += va.w;
    }
    ((float4*)(g_agg1 + (size_t)n * HID))[l] = acc;
}

// ---------------- GEMM2: m2 = (relu(agg1*nd + b1) .* ns) @ W2  (128 -> 64) ---
__global__ void __launch_bounds__(256)
k_gemm2(const float* __restrict__ b1, const float* __restrict__ W2) {
    __shared__ float sW[HID * OUT_F];  // 32KB
    __shared__ float sh[16 * HID];     // 8KB
    int t = threadIdx.x;

    float4* sW4 = (float4*)sW;
    const float4* W24 = (const float4*)W2;
    for (int i = t; i < HID * OUT_F / 4; i += 256) sW4[i] = W24[i];

    int j  = t & (OUT_F - 1);
    int ng = t >> 6;  // 0..3

    for (int tile = blockIdx.x; tile < N_NODES / 16; tile += gridDim.x) {
        int base = tile * 16;
        __syncthreads();
        for (int i = t; i < 16 * HID / 4; i += 256) {
            int n = i >> 5;
            int kk = i & 31;
            int node = base + n;
            float nd = g_nd[node];
            float ns = g_ns[node];
            float4 v  = ((const float4*)(g_agg1 + (size_t)node * HID))[kk];
            float4 bv = ((const float4*)b1)[kk];
            float4 h;
            h.x = fmaxf(v.x * nd + bv.x, 0.f) * ns;
            h.y = fmaxf(v.y * nd + bv.y, 0.f) * ns;
            h.z = fmaxf(v.z * nd + bv.z, 0.f) * ns;
            h.w = fmaxf(v.w * nd + bv.w, 0.f) * ns;
            ((float4*)(sh + n * HID))[kk] = h;
        }
        __syncthreads();

        const float* h0 = sh + (ng * 4 + 0) * HID;
        const float* h1 = sh + (ng * 4 + 1) * HID;
        const float* h2 = sh + (ng * 4 + 2) * HID;
        const float* h3 = sh + (ng * 4 + 3) * HID;
        float acc0 = 0.f, acc1 = 0.f, acc2 = 0.f, acc3 = 0.f;
        #pragma unroll 8
        for (int k = 0; k < HID; k += 4) {
            float4 a0 = *(const float4*)(h0 + k);
            float4 a1 = *(const float4*)(h1 + k);
            float4 a2 = *(const float4*)(h2 + k);
            float4 a3 = *(const float4*)(h3 + k);
            float w0 = sW[(k + 0) * OUT_F + j];
            float w1 = sW[(k + 1) * OUT_F + j];
            float w2 = sW[(k + 2) * OUT_F + j];
            float w3 = sW[(k + 3) * OUT_F + j];
            acc0 += a0.x * w0 + a0.y * w1 + a0.z * w2 + a0.w * w3;
            acc1 += a1.x * w0 + a1.y * w1 + a1.z * w2 + a1.w * w3;
            acc2 += a2.x * w0 + a2.y * w1 + a2.z * w2 + a2.w * w3;
            acc3 += a3.x * w0 + a3.y * w1 + a3.z * w2 + a3.w * w3;
        }
        int nb = base + ng * 4;
        g_m2[(size_t)(nb + 0) * OUT_F + j] = acc0;
        g_m2[(size_t)(nb + 1) * OUT_F + j] = acc1;
        g_m2[(size_t)(nb + 2) * OUT_F + j] = acc2;
        g_m2[(size_t)(nb + 3) * OUT_F + j] = acc3;
    }
}

// ---------------- agg2 + finalize: out = (gather-sum m2) * nd + b2 -----------
// one warp per node; lane l owns float2 l of the 64-float row
__global__ void __launch_bounds__(256)
k_agg2(float* __restrict__ out, const float* __restrict__ b2) {
    int n = (blockIdx.x * 256 + threadIdx.x) >> 5;
    if (n >= N_NODES) return;
    int l = threadIdx.x & 31;
    int s0 = g_rowptr[n];
    int e1 = g_rowptr[n + 1];
    float2 acc = make_float2(0.f, 0.f);
    int e = s0;
    for (; e + 1 < e1; e += 2) {
        int sa = g_esrc[e];
        int sb = g_esrc[e + 1];
        float2 va = ((const float2*)(g_m2 + (size_t)sa * OUT_F))[l];
        float2 vb = ((const float2*)(g_m2 + (size_t)sb * OUT_F))[l];
        acc.x += va.x + vb.x;
        acc.y += va.y + vb.y;
    }
    if (e < e1) {
        int sa = g_esrc[e];
        float2 va = ((const float2*)(g_m2 + (size_t)sa * OUT_F))[l];
        acc.x += va.x; acc.y += va.y;
    }
    float nd = g_nd[n];
    float2 bv = ((const float2*)b2)[l];
    float2 r;
    r.x = acc.x * nd + bv.x;
    r.y = acc.y * nd + bv.y;
    ((float2*)(out + (size_t)n * OUT_F))[l] = r;
}

// ---------------- launch -----------------------------------------------------
extern "C" void kernel_launch(void* const* d_in, const int* in_sizes, int n_in,
                              void* d_out, int out_size) {
    // Identify inputs by element count (robust to any metadata ordering).
    const float *x = 0, *W1 = 0, *b1 = 0, *W2 = 0, *b2 = 0;
    const void *srcp = 0, *dstp = 0;
    for (int i = 0; i < n_in; i++) {
        switch (in_sizes[i]) {
            case N_NODES * IN_F: x  = (const float*)d_in[i]; break;   // 12,800,000
            case IN_F * HID:     W1 = (const float*)d_in[i]; break;   // 32,768
            case HID * OUT_F:    W2 = (const float*)d_in[i]; break;   // 8,192
            case HID:            b1 = (const float*)d_in[i]; break;   // 128
            case OUT_F:          b2 = (const float*)d_in[i]; break;   // 64
            case N_EDGES:                                              // 800,000 (x2)
                if (!srcp) srcp = d_in[i]; else dstp = d_in[i];
                break;
            default: break;
        }
    }
    float* out = (float*)d_out;

    k_init<<<(N_NODES + 255) / 256, 256>>>();
    k_detect<<<(N_EDGES / 2 + 255) / 256, 256>>>((const int*)srcp, (const int*)dstp);
    k_cvt<<<(N_EDGES + 255) / 256, 256>>>(srcp, dstp);
    k_deg<<<(N_EDGES + 255) / 256, 256>>>();
    k_norms<<<(N_NODES + 255) / 256, 256>>>();
    k_scan1<<<SCAN_NBLK, SCAN_B>>>();
    k_scan2<<<1, 32>>>();
    k_scan3<<<SCAN_NBLK, SCAN_B>>>();
    k_fill<<<(N_EDGES + 255) / 256, 256>>>();
    k_gemm1<<<(N_NODES + 127) / 128, 256>>>(x, W1);
    k_agg1<<<(N_NODES * 32) / 256, 256>>>();
    k_gemm2<<<592, 256>>>(b1, W2);
    k_agg2<<<(N_NODES * 32) / 256, 256>>>(out, b2);
}

// round 10
// speedup vs baseline: 1.0267x; 1.0267x over previous
#include <cuda_runtime.h>
#include <cstdint>

#define N_NODES 50000
#define N_EDGES 800000
#define IN_F 256
#define HID 128
#define OUT_F 64

#define SCAN_B 512
#define SCAN_NBLK ((N_NODES + SCAN_B - 1) / SCAN_B)   // 98

// ---------------- scratch (device globals; no allocs allowed) ----------------
__device__ __align__(16) float g_m1[(size_t)N_NODES * HID];    // (x*ns) @ W1
__device__ __align__(16) float g_agg1[(size_t)N_NODES * HID];  // gather accum, layer 1
__device__ __align__(16) float g_m2[(size_t)N_NODES * OUT_F];  // (h*ns) @ W2
__device__ float g_ns[N_NODES];                  // deg_out^-1/2 (clamped)
__device__ float g_nd[N_NODES];                  // deg_in^-1/2 (clamped)
__device__ int   g_degs[N_NODES];                // out-degree (src)
__device__ int   g_degd[N_NODES];                // in-degree (dst)
__device__ int   g_rowptr[N_NODES + 1];          // CSR by dst
__device__ int   g_cur[N_NODES];                 // fill cursors
__device__ int   g_esrc[N_EDGES];                // src id per bucketed edge
__device__ int   g_src[N_EDGES];                 // normalized (int, clamped) src
__device__ int   g_dst[N_EDGES];                 // normalized (int, clamped) dst
__device__ int   g_bsum[SCAN_NBLK];
__device__ int   g_is32;                         // 1 if index arrays are int32

// ---------------- init ------------------------------------------------------
__global__ void k_init() {
    int i = blockIdx.x * blockDim.x + threadIdx.x;
    if (i < N_NODES) { g_degs[i] = 0; g_degd[i] = 0; }
    if (i == 0) g_is32 = 0;
}

// ---------------- dtype detect: int32 vs int64 indices -----------------------
// Reading the first N_EDGES int32 words is safe for BOTH dtypes. If the data
// is little-endian int64 with values < 2^31, every odd word is 0.
__global__ void k_detect(const int* __restrict__ sw, const int* __restrict__ dw) {
    int t = blockIdx.x * 256 + threadIdx.x;
    int v = 0;
    if (t < N_EDGES / 2) v = sw[2 * t + 1] | dw[2 * t + 1];
    unsigned any = __ballot_sync(0xffffffffu, v != 0);
    if ((threadIdx.x & 31) == 0 && any) atomicOr(&g_is32, 1);
}

// ---------------- normalize indices + count degrees (fused) ------------------
__global__ void k_cvtdeg(const void* __restrict__ srcp, const void* __restrict__ dstp) {
    int e = blockIdx.x * 256 + threadIdx.x;
    if (e >= N_EDGES) return;
    int s, d;
    if (g_is32) {
        s = ((const int*)srcp)[e];
        d = ((const int*)dstp)[e];
    } else {
        s = (int)((const long long*)srcp)[e];
        d = (int)((const long long*)dstp)[e];
    }
    s = min(max(s, 0), N_NODES - 1);
    d = min(max(d, 0), N_NODES - 1);
    g_src[e] = s;
    g_dst[e] = d;
    atomicAdd(&g_degs[s], 1);
    atomicAdd(&g_degd[d], 1);
}

// ---------------- scan pass 1: block-local exclusive scan + norms ------------
__global__ void k_scan1() {
    __shared__ int sh[SCAN_B];
    int i = blockIdx.x * SCAN_B + threadIdx.x;
    int v = (i < N_NODES) ? g_degd[i] : 0;
    sh[threadIdx.x] = v;
    __syncthreads();
    #pragma unroll
    for (int off = 1; off < SCAN_B; off <<= 1) {
        int t = (threadIdx.x >= off) ? sh[threadIdx.x - off] : 0;
        __syncthreads();
        sh[threadIdx.x] += t;
        __syncthreads();
    }
    if (i < N_NODES) {
        g_rowptr[i] = sh[threadIdx.x] - v;   // exclusive
        int ds = g_degs[i]; if (ds < 1) ds = 1;
        int dd = v;         if (dd < 1) dd = 1;
        g_ns[i] = rsqrtf((float)ds);
        g_nd[i] = rsqrtf((float)dd);
    }
    if (threadIdx.x == SCAN_B - 1) g_bsum[blockIdx.x] = sh[threadIdx.x];
}

// ---------------- scan pass 2: per-block prefix of bsum + apply + cur=0 ------
// Each block computes its own prefix (98 values, parallel loads + warp reduce)
// instead of a serial single-thread scan kernel.
__global__ void k_scan3() {
    __shared__ int warpsum[4];
    int t = threadIdx.x;
    int v = 0;
    if (t < 128) {
        if (t < SCAN_NBLK && t < (int)blockIdx.x) v = g_bsum[t];
        #pragma unroll
        for (int o = 16; o > 0; o >>= 1) v += __shfl_down_sync(0xffffffffu, v, o);
        if ((t & 31) == 0) warpsum[t >> 5] = v;
    }
    __syncthreads();
    int off = warpsum[0] + warpsum[1] + warpsum[2] + warpsum[3];
    int i = blockIdx.x * SCAN_B + t;
    if (i < N_NODES) { g_rowptr[i] += off; g_cur[i] = 0; }
    if (i == 0) g_rowptr[N_NODES] = N_EDGES;
}

// ---------------- bucket fill: edges grouped by dst --------------------------
__global__ void k_fill() {
    int e = blockIdx.x * blockDim.x + threadIdx.x;
    if (e >= N_EDGES) return;
    int d = g_dst[e];
    int pos = g_rowptr[d] + atomicAdd(&g_cur[d], 1);
    if (pos >= 0 && pos < N_EDGES) g_esrc[pos] = g_src[e];
}

// ---------------- GEMM1: m1 = (x .* ns) @ W1  (50000x256 @ 256x128) ----------
// Classic tiled SGEMM: 128x128 tile, 256 threads, 8x8 microtile, KC=16.
#define KC 16
__global__ void __launch_bounds__(256)
k_gemm1(const float* __restrict__ x, const float* __restrict__ W1) {
    __shared__ float xs[KC][132];   // [k][m], padded to dodge STS conflicts
    __shared__ float ws[KC][128];   // [k][n]
    int t = threadIdx.x;
    int base = blockIdx.x * 128;
    int m0 = (t >> 4) * 8;
    int n0 = (t & 15) * 8;
    float acc[8][8] = {};

    for (int k0 = 0; k0 < IN_F; k0 += KC) {
        __syncthreads();
        #pragma unroll
        for (int f = t; f < 512; f += 256) {
            int kk = f >> 5;
            int nn = (f & 31) * 4;
            *(float4*)(&ws[kk][nn]) = *(const float4*)(W1 + (k0 + kk) * HID + nn);
        }
        #pragma unroll
        for (int f = t; f < 512; f += 256) {
            int mm = f >> 2;
            int k4 = (f & 3) * 4;
            int node = base + mm; if (node >= N_NODES) node = N_NODES - 1;
            float ns = g_ns[node];
            float4 v = *(const float4*)(x + (size_t)node * IN_F + k0 + k4);
            xs[k4 + 0][mm] = v.x * ns;
            xs[k4 + 1][mm] = v.y * ns;
            xs[k4 + 2][mm] = v.z * ns;
            xs[k4 + 3][mm] = v.w * ns;
        }
        __syncthreads();
        #pragma unroll
        for (int k = 0; k < KC; k++) {
            float a[8], b[8];
            *(float4*)(a)     = *(float4*)(&xs[k][m0]);
            *(float4*)(a + 4) = *(float4*)(&xs[k][m0 + 4]);
            *(float4*)(b)     = *(float4*)(&ws[k][n0]);
            *(float4*)(b + 4) = *(float4*)(&ws[k][n0 + 4]);
            #pragma unroll
            for (int i = 0; i < 8; i++)
                #pragma unroll
                for (int j = 0; j < 8; j++)
                    acc[i][j] += a[i] * b[j];
        }
    }
    #pragma unroll
    for (int i = 0; i < 8; i++) {
        int node = base + m0 + i;
        if (node < N_NODES) {
            *(float4*)(g_m1 + (size_t)node * HID + n0)     = *(float4*)(&acc[i][0]);
            *(float4*)(g_m1 + (size_t)node * HID + n0 + 4) = *(float4*)(&acc[i][4]);
        }
    }
}

// ---------------- agg1: gather-sum m1 rows per dst (CSR) ---------------------
// one warp per node; lane l owns float4 l of the 128-float row; 4-edge unroll
__global__ void __launch_bounds__(256)
k_agg1() {
    int n = (blockIdx.x * 256 + threadIdx.x) >> 5;
    if (n >= N_NODES) return;
    int l = threadIdx.x & 31;
    int s0 = g_rowptr[n];
    int e1 = g_rowptr[n + 1];
    float4 acc = make_float4(0.f, 0.f, 0.f, 0.f);
    int e = s0;
    for (; e + 3 < e1; e += 4) {
        int sa = g_esrc[e];
        int sb = g_esrc[e + 1];
        int sc = g_esrc[e + 2];
        int sd = g_esrc[e + 3];
        float4 va = ((const float4*)(g_m1 + (size_t)sa * HID))[l];
        float4 vb = ((const float4*)(g_m1 + (size_t)sb * HID))[l];
        float4 vc = ((const float4*)(g_m1 + (size_t)sc * HID))[l];
        float4 vd = ((const float4*)(g_m1 + (size_t)sd * HID))[l];
        acc.x += (va.x + vb.x) + (vc.x + vd.x);
        acc.y += (va.y + vb.y) + (vc.y + vd.y);
        acc.z += (va.z + vb.z) + (vc.z + vd.z);
        acc.w += (va.w + vb.w) + (vc.w + vd.w);
    }
    for (; e < e1; e++) {
        int sa = g_esrc[e];
        float4 va = ((const float4*)(g_m1 + (size_t)sa * HID))[l];
        acc.x += va.x; acc.y += va.y; acc.z += va.z; acc.w += va.w;
    }
    ((float4*)(g_agg1 + (size_t)n * HID))[l] = acc;
}

// ---------------- GEMM2: m2 = (relu(agg1*nd + b1) .* ns) @ W2  (128 -> 64) ---
__global__ void __launch_bounds__(256)
k_gemm2(const float* __restrict__ b1, const float* __restrict__ W2) {
    __shared__ float sW[HID * OUT_F];  // 32KB
    __shared__ float sh[16 * HID];     // 8KB
    int t = threadIdx.x;

    float4* sW4 = (float4*)sW;
    const float4* W24 = (const float4*)W2;
    for (int i = t; i < HID * OUT_F / 4; i += 256) sW4[i] = W24[i];

    int j  = t & (OUT_F - 1);
    int ng = t >> 6;  // 0..3

    for (int tile = blockIdx.x; tile < N_NODES / 16; tile += gridDim.x) {
        int base = tile * 16;
        __syncthreads();
        for (int i = t; i < 16 * HID / 4; i += 256) {
            int n = i >> 5;
            int kk = i & 31;
            int node = base + n;
            float nd = g_nd[node];
            float ns = g_ns[node];
            float4 v  = ((const float4*)(g_agg1 + (size_t)node * HID))[kk];
            float4 bv = ((const float4*)b1)[kk];
            float4 h;
            h.x = fmaxf(v.x * nd + bv.x, 0.f) * ns;
            h.y = fmaxf(v.y * nd + bv.y, 0.f) * ns;
            h.z = fmaxf(v.z * nd + bv.z, 0.f) * ns;
            h.w = fmaxf(v.w * nd + bv.w, 0.f) * ns;
            ((float4*)(sh + n * HID))[kk] = h;
        }
        __syncthreads();

        const float* h0 = sh + (ng * 4 + 0) * HID;
        const float* h1 = sh + (ng * 4 + 1) * HID;
        const float* h2 = sh + (ng * 4 + 2) * HID;
        const float* h3 = sh + (ng * 4 + 3) * HID;
        float acc0 = 0.f, acc1 = 0.f, acc2 = 0.f, acc3 = 0.f;
        #pragma unroll 8
        for (int k = 0; k < HID; k += 4) {
            float4 a0 = *(const float4*)(h0 + k);
            float4 a1 = *(const float4*)(h1 + k);
            float4 a2 = *(const float4*)(h2 + k);
            float4 a3 = *(const float4*)(h3 + k);
            float w0 = sW[(k + 0) * OUT_F + j];
            float w1 = sW[(k + 1) * OUT_F + j];
            float w2 = sW[(k + 2) * OUT_F + j];
            float w3 = sW[(k + 3) * OUT_F + j];
            acc0 += a0.x * w0 + a0.y * w1 + a0.z * w2 + a0.w * w3;
            acc1 += a1.x * w0 + a1.y * w1 + a1.z * w2 + a1.w * w3;
            acc2 += a2.x * w0 + a2.y * w1 + a2.z * w2 + a2.w * w3;
            acc3 += a3.x * w0 + a3.y * w1 + a3.z * w2 + a3.w * w3;
        }
        int nb = base + ng * 4;
        g_m2[(size_t)(nb + 0) * OUT_F + j] = acc0;
        g_m2[(size_t)(nb + 1) * OUT_F + j] = acc1;
        g_m2[(size_t)(nb + 2) * OUT_F + j] = acc2;
        g_m2[(size_t)(nb + 3) * OUT_F + j] = acc3;
    }
}

// ---------------- agg2 + finalize: out = (gather-sum m2) * nd + b2 -----------
// one warp per node; lane l owns float2 l of the 64-float row; 4-edge unroll
__global__ void __launch_bounds__(256)
k_agg2(float* __restrict__ out, const float* __restrict__ b2) {
    int n = (blockIdx.x * 256 + threadIdx.x) >> 5;
    if (n >= N_NODES) return;
    int l = threadIdx.x & 31;
    int s0 = g_rowptr[n];
    int e1 = g_rowptr[n + 1];
    float2 acc = make_float2(0.f, 0.f);
    int e = s0;
    for (; e + 3 < e1; e += 4) {
        int sa = g_esrc[e];
        int sb = g_esrc[e + 1];
        int sc = g_esrc[e + 2];
        int sd = g_esrc[e + 3];
        float2 va = ((const float2*)(g_m2 + (size_t)sa * OUT_F))[l];
        float2 vb = ((const float2*)(g_m2 + (size_t)sb * OUT_F))[l];
        float2 vc = ((const float2*)(g_m2 + (size_t)sc * OUT_F))[l];
        float2 vd = ((const float2*)(g_m2 + (size_t)sd * OUT_F))[l];
        acc.x += (va.x + vb.x) + (vc.x + vd.x);
        acc.y += (va.y + vb.y) + (vc.y + vd.y);
    }
    for (; e < e1; e++) {
        int sa = g_esrc[e];
        float2 va = ((const float2*)(g_m2 + (size_t)sa * OUT_F))[l];
        acc.x += va.x; acc.y += va.y;
    }
    float nd = g_nd[n];
    float2 bv = ((const float2*)b2)[l];
    float2 r;
    r.x = acc.x * nd + bv.x;
    r.y = acc.y * nd + bv.y;
    ((float2*)(out + (size_t)n * OUT_F))[l] = r;
}

// ---------------- launch -----------------------------------------------------
extern "C" void kernel_launch(void* const* d_in, const int* in_sizes, int n_in,
                              void* d_out, int out_size) {
    // Identify inputs by element count (robust to any metadata ordering).
    const float *x = 0, *W1 = 0, *b1 = 0, *W2 = 0, *b2 = 0;
    const void *srcp = 0, *dstp = 0;
    for (int i = 0; i < n_in; i++) {
        switch (in_sizes[i]) {
            case N_NODES * IN_F: x  = (const float*)d_in[i]; break;   // 12,800,000
            case IN_F * HID:     W1 = (const float*)d_in[i]; break;   // 32,768
            case HID * OUT_F:    W2 = (const float*)d_in[i]; break;   // 8,192
            case HID:            b1 = (const float*)d_in[i]; break;   // 128
            case OUT_F:          b2 = (const float*)d_in[i]; break;   // 64
            case N_EDGES:                                              // 800,000 (x2)
                if (!srcp) srcp = d_in[i]; else dstp = d_in[i];
                break;
            default: break;
        }
    }
    float* out = (float*)d_out;

    k_init<<<(N_NODES + 255) / 256, 256>>>();
    k_detect<<<(N_EDGES / 2 + 255) / 256, 256>>>((const int*)srcp, (const int*)dstp);
    k_cvtdeg<<<(N_EDGES + 255) / 256, 256>>>(srcp, dstp);
    k_scan1<<<SCAN_NBLK, SCAN_B>>>();
    k_scan3<<<SCAN_NBLK, SCAN_B>>>();
    k_fill<<<(N_EDGES + 255) / 256, 256>>>();
    k_gemm1<<<(N_NODES + 127) / 128, 256>>>(x, W1);
    k_agg1<<<(N_NODES * 32) / 256, 256>>>();
    k_gemm2<<<592, 256>>>(b1, W2);
    k_agg2<<<(N_NODES * 32) / 256, 256>>>(out, b2);
}